// round 7
// baseline (speedup 1.0000x reference)
#include <cuda_runtime.h>
#include <cuda_bf16.h>
#include <cstdint>
#include <cstddef>

// ---------------- problem constants ----------------
#define B_SZ   256
#define T_SZ   1024
#define I_SZ   128
#define H_SZ   256
#define CLC    8                 // CTAs per cluster (hidden split)
#define NB     16                // batch rows per cluster
#define GRID_CTAS 128
#define THREADS2 512             // recurrent kernel: 16 warps

// ---------------- recurrent kernel SMEM ----------------
// A: [128 rows][SA2] bf16, cols 0..255 hi, 256..511 lo (short-weights only)
// Bs: ping-pong [2][16 rows][SB2] bf16, cols 0..255 hi, 256..511 lo
// scr: [2][128][20] fp32 K-split partials
#define SA2 520                              // 1040B = 65*16B odd -> conflict-free ldmatrix
#define SB2 520
#define A_BYTES2 (128 * SA2 * 2)             // 133120
#define B_OFF2   A_BYTES2
#define B_BYTES2 (NB * SB2 * 2)              // 16640 per buffer
#define SCR_OFF2 (B_OFF2 + 2 * B_BYTES2)     // 166400
#define SCR_S    20
#define SMEM2    (SCR_OFF2 + 2 * 128 * SCR_S * 4)  // 207360

// ---------------- precompute kernel SMEM ----------------
#define SA3 264                              // 528B = 33*16B odd
#define PC_A_BYTES (128 * SA3 * 2)           // 67584 (x tile, 128 rows)
#define PC_B_BYTES (64 * SA3 * 2)            // 33792 (W tile, 64 rows)
#define SMEM3 (PC_A_BYTES + PC_B_BYTES)      // 101376 -> 2 CTAs/SM

// x-projection scratch: xp[t*B + b][g*256 + h], fp32, 1 GiB
__device__ float g_xproj[268435456];

// ---------------- helpers ----------------
__device__ __forceinline__ uint32_t smem_u32(const void* p) {
    uint32_t a;
    asm("{ .reg .u64 t; cvta.to.shared.u64 t, %1; cvt.u32.u64 %0, t; }" : "=r"(a) : "l"(p));
    return a;
}
__device__ __forceinline__ void cluster_sync() {
    asm volatile("barrier.cluster.arrive.aligned;" ::: "memory");
    asm volatile("barrier.cluster.wait.aligned;"   ::: "memory");
}
__device__ __forceinline__ void ldsm4(uint32_t* r, uint32_t addr) {
    asm volatile("ldmatrix.sync.aligned.m8n8.x4.shared.b16 {%0,%1,%2,%3}, [%4];"
                 : "=r"(r[0]), "=r"(r[1]), "=r"(r[2]), "=r"(r[3]) : "r"(addr));
}
__device__ __forceinline__ void mma16816(float* d, const uint32_t* a, const uint32_t* b) {
    asm volatile("mma.sync.aligned.m16n8k16.row.col.f32.bf16.bf16.f32 "
                 "{%0,%1,%2,%3}, {%4,%5,%6,%7}, {%8,%9}, {%0,%1,%2,%3};"
                 : "+f"(d[0]), "+f"(d[1]), "+f"(d[2]), "+f"(d[3])
                 : "r"(a[0]), "r"(a[1]), "r"(a[2]), "r"(a[3]), "r"(b[0]), "r"(b[1]));
}
__device__ __forceinline__ float sigm(float x) {
    return __fdividef(1.0f, 1.0f + __expf(-x));
}
__device__ __forceinline__ float tanh_(float x) {
    float e = __expf(-2.0f * fabsf(x));
    return copysignf(__fdividef(1.0f - e, 1.0f + e), x);
}
__device__ __forceinline__ void split_bf16(float v, __nv_bfloat16& hi, __nv_bfloat16& lo) {
    hi = __float2bfloat16_rn(v);
    lo = __float2bfloat16_rn(v - __bfloat162float(hi));
}

// ================= precompute kernel: xp = x @ Wx (all gates, all t) =================
// Block: t-halfbatch on x-axis; (gate, hidden-quarter) on y-axis. N=64 -> 2 CTAs/SM.
__global__ void __launch_bounds__(256, 2)
xproj_kernel(const float* __restrict__ x,
             const float* __restrict__ Wf_x, const float* __restrict__ Wip_x,
             const float* __restrict__ Wit_x, const float* __restrict__ Wo_x)
{
    extern __shared__ char smem[];
    __nv_bfloat16* Ax = (__nv_bfloat16*)smem;                  // [128][264] hi|lo
    __nv_bfloat16* Bw = (__nv_bfloat16*)(smem + PC_A_BYTES);   // [64][264]  hi|lo

    const int tid = threadIdx.x;
    const int w   = tid >> 5;
    const int l   = tid & 31;
    const int t   = blockIdx.x >> 1;
    const int bh  = (blockIdx.x & 1) * 128;          // batch half
    const int g   = blockIdx.y >> 2;
    const int hq  = (blockIdx.y & 3) * 64;           // hidden quarter
    const float* Wxg = (g == 0) ? Wf_x : (g == 1) ? Wip_x : (g == 2) ? Wit_x : Wo_x;

    // stage A = x block [128 b][128 i], split hi/lo
    {
        const int r    = tid >> 1;
        const int half = (tid & 1) * 64;
        const float* xr = x + ((size_t)(bh + r) * T_SZ + t) * I_SZ + half;
        #pragma unroll 4
        for (int q = 0; q < 64; q++) {
            __nv_bfloat16 hi, lo;
            split_bf16(xr[q], hi, lo);
            Ax[r * SA3 + half + q]       = hi;
            Ax[r * SA3 + 128 + half + q] = lo;
        }
    }
    // stage B = W [64 n(h)][128 k(i)], split hi/lo
    {
        const int kk = tid >> 1;                     // 0..127
        const int nh = (tid & 1) * 32;
        const float* wr = Wxg + (size_t)kk * H_SZ + hq + nh;
        #pragma unroll 4
        for (int n = 0; n < 32; n++) {
            __nv_bfloat16 hi, lo;
            split_bf16(wr[n], hi, lo);
            Bw[(nh + n) * SA3 + kk]       = hi;
            Bw[(nh + n) * SA3 + 128 + kk] = lo;
        }
    }
    __syncthreads();

    const uint32_t a_lane = smem_u32(Ax) +
        (uint32_t)(((16 * w + (l & 7) + 8 * ((l >> 3) & 1)) * SA3 + 8 * (l >> 4)) * 2);
    const uint32_t b_lane = smem_u32(Bw) +
        (uint32_t)((((l & 7) + 8 * (l >> 4)) * SA3 + 8 * ((l >> 3) & 1)) * 2);

    float acc[8][4];
    #pragma unroll
    for (int i = 0; i < 8; i++)
        #pragma unroll
        for (int j = 0; j < 4; j++) acc[i][j] = 0.0f;

    #pragma unroll 2
    for (int kc = 0; kc < 8; kc++) {
        uint32_t ah[4], al[4];
        ldsm4(ah, a_lane + kc * 32);
        ldsm4(al, a_lane + 256 + kc * 32);          // lo at +128 els
        #pragma unroll
        for (int nt = 0; nt < 4; nt++) {
            uint32_t bh4[4], bl4[4];
            uint32_t ba = b_lane + (uint32_t)(nt * 16 * SA3 * 2) + kc * 32;
            ldsm4(bh4, ba);
            ldsm4(bl4, ba + 256);
            mma16816(acc[2 * nt],     ah, bh4 + 0);
            mma16816(acc[2 * nt + 1], ah, bh4 + 2);
            mma16816(acc[2 * nt],     al, bh4 + 0);
            mma16816(acc[2 * nt + 1], al, bh4 + 2);
            mma16816(acc[2 * nt],     ah, bl4 + 0);
            mma16816(acc[2 * nt + 1], ah, bl4 + 2);
        }
    }

    // store to xp
    {
        const size_t row0 = (size_t)t * B_SZ + bh + 16 * w + (l >> 2);
        const int    cb   = g * 256 + hq + (l & 3) * 2;
        #pragma unroll
        for (int nt = 0; nt < 4; nt++) {
            *(float2*)&g_xproj[row0 * 1024 + cb + nt * 16]           = make_float2(acc[2*nt][0], acc[2*nt][1]);
            *(float2*)&g_xproj[(row0 + 8) * 1024 + cb + nt * 16]     = make_float2(acc[2*nt][2], acc[2*nt][3]);
            *(float2*)&g_xproj[row0 * 1024 + cb + nt * 16 + 8]       = make_float2(acc[2*nt+1][0], acc[2*nt+1][1]);
            *(float2*)&g_xproj[(row0 + 8) * 1024 + cb + nt * 16 + 8] = make_float2(acc[2*nt+1][2], acc[2*nt+1][3]);
        }
    }
}

// ================= recurrent kernel =================
__global__ void __launch_bounds__(THREADS2, 1) __cluster_dims__(CLC, 1, 1)
lstm_rec_kernel(const float* __restrict__ Wf_h,  const float* __restrict__ bf,
                const float* __restrict__ Wip_h, const float* __restrict__ bip,
                const float* __restrict__ Wit_h, const float* __restrict__ bit_,
                const float* __restrict__ Wo_h,  const float* __restrict__ bo,
                float* __restrict__ out)
{
    extern __shared__ char smem[];
    __nv_bfloat16* As = (__nv_bfloat16*)smem;
    float*         scr = (float*)(smem + SCR_OFF2);   // [2][128][20]
    const uint32_t sbBs = smem_u32(smem) + B_OFF2;    // base of Bs[0]

    const int tid = threadIdx.x;
    const int w   = tid >> 5;
    const int l   = tid & 31;
    const int m   = w & 7;                  // M-tile (16 gate rows)
    const int ks  = w >> 3;                 // K half (chunks ks*8 .. ks*8+7)
    const int cc  = blockIdx.x & (CLC - 1); // cluster rank = hidden-slice owner
    const int grp = blockIdx.x >> 3;
    const int b0  = grp * NB;

    // ---- stage A (short-part weights, K=256) hi|lo into SMEM ----
    {
        const int r  = tid >> 2;            // 0..127 : row = 4*h_local + gate
        const int kq = (tid & 3) * 64;
        const int g  = r & 3;
        const int hs = 32 * cc + (r >> 2);
        const float* Wh = (g == 0) ? Wf_h : (g == 1) ? Wip_h : (g == 2) ? Wit_h : Wo_h;
        #pragma unroll 4
        for (int k = kq; k < kq + 64; k++) {
            __nv_bfloat16 hi, lo;
            split_bf16(Wh[(size_t)k * H_SZ + hs], hi, lo);
            As[r * SA2 + k]       = hi;
            As[r * SA2 + 256 + k] = lo;
        }
    }
    // ---- zero Bs[0] (step-0 short state = 0) ----
    for (int i = tid; i < B_BYTES2 / 4; i += THREADS2)
        ((uint32_t*)(smem + B_OFF2))[i] = 0u;
    __syncthreads();

    // ---- load A fragments into registers (once) ----
    uint32_t ah[8][4], al[8][4];
    {
        const uint32_t a_lane = smem_u32(As) +
            (uint32_t)(((16 * m + (l & 7) + 8 * ((l >> 3) & 1)) * SA2 + 8 * (l >> 4)) * 2);
        #pragma unroll
        for (int kc = 0; kc < 8; kc++) {
            ldsm4(ah[kc], a_lane + (ks * 8 + kc) * 32);
            ldsm4(al[kc], a_lane + 512 + (ks * 8 + kc) * 32);   // lo at +256 els
        }
    }

    const uint32_t b_lane0 = sbBs +
        (uint32_t)((((l & 7) + 8 * (l >> 4)) * SB2 + 8 * ((l >> 3) & 1)) * 2);

    // ---- epilogue mapping: 1 cell per thread: hl = tid>>4, bb = tid&15 ----
    const int hl = tid >> 4;                 // = 2w + (l>>4)
    const int bb = tid & 15;                 // = l & 15
    const int hg = 32 * cc + hl;
    const float biasv[4] = {bf[hg], bip[hg], bit_[hg], bo[hg]};
    float longv = 0.0f;

    // remote-push address pieces (element offset within a Bs buffer)
    const uint32_t push_elem = (uint32_t)bb * SB2 + ((l < 16) ? (32 * cc + 2 * w)
                                                              : (256 + 32 * cc + 2 * w));

    __syncthreads();
    cluster_sync();

    #pragma unroll 1
    for (int t = 0; t < T_SZ; t++) {
        const int cur = t & 1;
        const int nxt = cur ^ 1;

        // ===== prefetch x-projection for this step (consumed in epilogue) =====
        float xpv[4];
        {
            const float* xr = g_xproj + ((size_t)t * B_SZ + b0 + bb) * 1024 + hg;
            #pragma unroll
            for (int g = 0; g < 4; g++) xpv[g] = __ldcg(xr + g * 256);
        }

        // ===== GEMM from Bs[cur]: 3-term bf16 split, A frags in registers =====
        float a0h[4] = {0.f,0.f,0.f,0.f}, a0c[4] = {0.f,0.f,0.f,0.f};
        float a1h[4] = {0.f,0.f,0.f,0.f}, a1c[4] = {0.f,0.f,0.f,0.f};
        {
            const uint32_t bl_base = b_lane0 + (uint32_t)cur * B_BYTES2;
            #pragma unroll
            for (int kc = 0; kc < 8; kc++) {
                uint32_t bh4[4], bl4[4];
                const uint32_t kb = (uint32_t)(ks * 8 + kc) * 32;
                ldsm4(bh4, bl_base + kb);
                ldsm4(bl4, bl_base + 512 + kb);
                mma16816(a0h, ah[kc], bh4 + 0);
                mma16816(a1h, ah[kc], bh4 + 2);
                mma16816(a0c, al[kc], bh4 + 0);
                mma16816(a1c, al[kc], bh4 + 2);
                mma16816(a0c, ah[kc], bl4 + 0);
                mma16816(a1c, ah[kc], bl4 + 2);
            }
        }

        // ===== store K-split partials to scratch =====
        {
            float* s = scr + ks * (128 * SCR_S);
            const int r0 = 16 * m + (l >> 2);
            const int c0 = (l & 3) * 2;
            *(float2*)&s[r0 * SCR_S + c0]           = make_float2(a0h[0] + a0c[0], a0h[1] + a0c[1]);
            *(float2*)&s[(r0 + 8) * SCR_S + c0]     = make_float2(a0h[2] + a0c[2], a0h[3] + a0c[3]);
            *(float2*)&s[r0 * SCR_S + c0 + 8]       = make_float2(a1h[0] + a1c[0], a1h[1] + a1c[1]);
            *(float2*)&s[(r0 + 8) * SCR_S + c0 + 8] = make_float2(a1h[2] + a1c[2], a1h[3] + a1c[3]);
        }
        __syncthreads();

        // ===== epilogue: 1 cell (hl, bb); push new_short into all peers' Bs[nxt] =====
        {
            float z[4];
            #pragma unroll
            for (int g = 0; g < 4; g++) {
                const int r = 4 * hl + g;
                z[g] = scr[r * SCR_S + bb] + scr[128 * SCR_S + r * SCR_S + bb]
                     + xpv[g] + biasv[g];
            }
            float f  = sigm(z[0]);
            float ip = sigm(z[1]);
            float pt = tanh_(z[2]);
            longv = f * longv + ip * pt;
            float o  = sigm(z[3]);
            float ns = tanh_(longv) * o;

            __nv_bfloat16 hi, lo;
            split_bf16(ns, hi, lo);
            uint32_t pk = (uint32_t)__bfloat16_as_ushort(hi) |
                          ((uint32_t)__bfloat16_as_ushort(lo) << 16);

            // pair up: lanes 0-15 hold even-hl cells, 16-31 odd-hl (same bb)
            uint32_t other = __shfl_xor_sync(0xffffffffu, pk, 16);
            uint32_t val = (l < 16) ? ((pk & 0xFFFFu) | (other << 16))
                                    : ((other >> 16) | (pk & 0xFFFF0000u));
            uint32_t laddr = sbBs + (uint32_t)nxt * B_BYTES2 + push_elem * 2;
            #pragma unroll
            for (int d = 0; d < CLC; d++) {
                uint32_t raddr;
                asm volatile("mapa.shared::cluster.u32 %0, %1, %2;"
                             : "=r"(raddr) : "r"(laddr), "r"(d));
                asm volatile("st.shared::cluster.u32 [%0], %1;"
                             :: "r"(raddr), "r"(val) : "memory");
            }

            if (t == T_SZ - 1) {
                const int bbg = b0 + bb;
                out[(size_t)bbg * H_SZ + hg]                       = ns;
                out[(size_t)B_SZ * H_SZ + (size_t)bbg * H_SZ + hg] = longv;
            }
        }

        cluster_sync();  // completes remote pushes; guards Bs/scr reuse
    }
}

// ---------------- launch ----------------
extern "C" void kernel_launch(void* const* d_in, const int* in_sizes, int n_in,
                              void* d_out, int out_size)
{
    (void)in_sizes; (void)n_in; (void)out_size;
    const float* x     = (const float*)d_in[0];
    const float* Wf_h  = (const float*)d_in[1];
    const float* Wf_x  = (const float*)d_in[2];
    const float* bf    = (const float*)d_in[3];
    const float* Wip_h = (const float*)d_in[4];
    const float* Wip_x = (const float*)d_in[5];
    const float* bip   = (const float*)d_in[6];
    const float* Wit_h = (const float*)d_in[7];
    const float* Wit_x = (const float*)d_in[8];
    const float* bit_  = (const float*)d_in[9];
    const float* Wo_h  = (const float*)d_in[10];
    const float* Wo_x  = (const float*)d_in[11];
    const float* bo    = (const float*)d_in[12];
    float* out = (float*)d_out;

    cudaFuncSetAttribute(xproj_kernel,
                         cudaFuncAttributeMaxDynamicSharedMemorySize, SMEM3);
    cudaFuncSetAttribute(lstm_rec_kernel,
                         cudaFuncAttributeMaxDynamicSharedMemorySize, SMEM2);

    dim3 pgrid(2048, 16);
    xproj_kernel<<<pgrid, 256, SMEM3>>>(x, Wf_x, Wip_x, Wit_x, Wo_x);

    lstm_rec_kernel<<<GRID_CTAS, THREADS2, SMEM2>>>(
        Wf_h, bf, Wip_h, bip, Wit_h, bit_, Wo_h, bo, out);
}

// round 8
// speedup vs baseline: 1.4956x; 1.4956x over previous
#include <cuda_runtime.h>
#include <cuda_bf16.h>
#include <cstdint>
#include <cstddef>

// ---------------- problem constants ----------------
#define B_SZ   256
#define T_SZ   1024
#define I_SZ   128
#define H_SZ   256
#define CLC    8                 // CTAs per cluster (hidden split)
#define NGRP   16                // clusters
#define GRID_CTAS 128
#define THREADS2 512             // recurrent kernel: 16 warps
#define NBG    8                 // batch rows per group (2 groups per cluster)

// ---------------- recurrent kernel SMEM ----------------
#define SA2 520                              // 1040B = 65*16B odd -> conflict-free ldmatrix
#define SB2 520
#define A_BYTES2  (128 * SA2 * 2)            // 133120
#define B_OFF2    A_BYTES2
#define BG_BYTES  (NBG * SB2 * 2)            // 8320 per group tile
#define SCR_OFF2  (B_OFF2 + 2 * BG_BYTES)    // 149760
#define SCR_S     12
#define MBAR_OFF  (SCR_OFF2 + 2 * 128 * SCR_S * 4)   // 162048
#define SMEM2     (MBAR_OFF + 64)            // 162112

// ---------------- precompute kernel SMEM ----------------
#define SA3 264                              // 528B = 33*16B odd
#define PC_A_BYTES (128 * SA3 * 2)           // 67584 (x tile)
#define PC_B_BYTES (128 * SA3 * 2)           // 67584 (W tile)
#define SMEM3 (PC_A_BYTES + PC_B_BYTES)      // 135168

// x-projection scratch: xp[t*B + b][g*256 + h], fp32, 1 GiB
__device__ float g_xproj[268435456];
// packed (hi | lo<<16) bf16 short-state exchange, ping-pong, in L2
__device__ uint32_t g_short_pack[2][B_SZ * H_SZ];
// pre-split, transposed x-weights: [gate][h=256][k=128] packed (hi | lo<<16)
__device__ uint32_t g_wxt[4][256 * 128];

// ---------------- helpers ----------------
__device__ __forceinline__ uint32_t smem_u32(const void* p) {
    uint32_t a;
    asm("{ .reg .u64 t; cvta.to.shared.u64 t, %1; cvt.u32.u64 %0, t; }" : "=r"(a) : "l"(p));
    return a;
}
__device__ __forceinline__ void cluster_sync() {
    asm volatile("barrier.cluster.arrive.aligned;" ::: "memory");
    asm volatile("barrier.cluster.wait.aligned;"   ::: "memory");
}
__device__ __forceinline__ void ldsm4(uint32_t* r, uint32_t addr) {
    asm volatile("ldmatrix.sync.aligned.m8n8.x4.shared.b16 {%0,%1,%2,%3}, [%4];"
                 : "=r"(r[0]), "=r"(r[1]), "=r"(r[2]), "=r"(r[3]) : "r"(addr));
}
__device__ __forceinline__ void ldsm2(uint32_t* r, uint32_t addr) {
    asm volatile("ldmatrix.sync.aligned.m8n8.x2.shared.b16 {%0,%1}, [%2];"
                 : "=r"(r[0]), "=r"(r[1]) : "r"(addr));
}
__device__ __forceinline__ void mma16816(float* d, const uint32_t* a, const uint32_t* b) {
    asm volatile("mma.sync.aligned.m16n8k16.row.col.f32.bf16.bf16.f32 "
                 "{%0,%1,%2,%3}, {%4,%5,%6,%7}, {%8,%9}, {%0,%1,%2,%3};"
                 : "+f"(d[0]), "+f"(d[1]), "+f"(d[2]), "+f"(d[3])
                 : "r"(a[0]), "r"(a[1]), "r"(a[2]), "r"(a[3]), "r"(b[0]), "r"(b[1]));
}
__device__ __forceinline__ void mbar_init(uint32_t mbar, uint32_t cnt) {
    asm volatile("mbarrier.init.shared.b64 [%0], %1;" :: "r"(mbar), "r"(cnt) : "memory");
}
__device__ __forceinline__ void mbar_arrive_cluster(uint32_t local_mbar, uint32_t rank) {
    asm volatile("{\n\t.reg .b32 ra;\n\t"
                 "mapa.shared::cluster.u32 ra, %0, %1;\n\t"
                 "mbarrier.arrive.shared::cluster.b64 _, [ra];\n\t}"
                 :: "r"(local_mbar), "r"(rank) : "memory");
}
__device__ __forceinline__ void mbar_wait_parity(uint32_t mbar, uint32_t parity) {
    asm volatile("{\n\t.reg .pred P1;\n\t"
                 "WAIT_LOOP_%=:\n\t"
                 "mbarrier.try_wait.parity.acquire.cta.shared::cta.b64 P1, [%0], %1, 0x989680;\n\t"
                 "@P1 bra.uni WAIT_DONE_%=;\n\t"
                 "bra.uni WAIT_LOOP_%=;\n\t"
                 "WAIT_DONE_%=:\n\t}" :: "r"(mbar), "r"(parity) : "memory");
}
__device__ __forceinline__ float sigm(float x) {
    return __fdividef(1.0f, 1.0f + __expf(-x));
}
__device__ __forceinline__ float tanh_(float x) {
    float e = __expf(-2.0f * fabsf(x));
    return copysignf(__fdividef(1.0f - e, 1.0f + e), x);
}
__device__ __forceinline__ void split_bf16(float v, __nv_bfloat16& hi, __nv_bfloat16& lo) {
    hi = __float2bfloat16_rn(v);
    lo = __float2bfloat16_rn(v - __bfloat162float(hi));
}

// ================= wsplit: Wx -> split/transposed packed global =================
__global__ void __launch_bounds__(256)
wsplit_kernel(const float* __restrict__ Wf_x, const float* __restrict__ Wip_x,
              const float* __restrict__ Wit_x, const float* __restrict__ Wo_x)
{
    const int g = blockIdx.x;
    const float* W = (g == 0) ? Wf_x : (g == 1) ? Wip_x : (g == 2) ? Wit_x : Wo_x;
    for (int i = threadIdx.x; i < 256 * 128; i += 256) {
        const int n = i >> 7, k = i & 127;
        float v = W[(size_t)k * H_SZ + n];
        __nv_bfloat16 hi, lo;
        split_bf16(v, hi, lo);
        g_wxt[g][i] = (uint32_t)__bfloat16_as_ushort(hi) |
                      ((uint32_t)__bfloat16_as_ushort(lo) << 16);
    }
}

// ================= precompute kernel: xp = x @ Wx (all gates, all t) =================
__global__ void __launch_bounds__(256, 1)
xproj_kernel(const float* __restrict__ x)
{
    extern __shared__ char smem[];
    __nv_bfloat16* Ax = (__nv_bfloat16*)smem;                  // [128][264] hi|lo
    __nv_bfloat16* Bw = (__nv_bfloat16*)(smem + PC_A_BYTES);   // [128][264] hi|lo

    const int tid = threadIdx.x;
    const int w   = tid >> 5;
    const int l   = tid & 31;
    const int t   = blockIdx.x >> 1;
    const int bh  = (blockIdx.x & 1) * 128;          // batch half
    const int g   = blockIdx.y >> 1;
    const int hb  = (blockIdx.y & 1) * 128;          // hidden half

    // stage A = x block [128 b][128 i], split hi/lo (coalesced reads, row STS)
    {
        const int r    = tid >> 1;
        const int half = (tid & 1) * 64;
        const float* xr = x + ((size_t)(bh + r) * T_SZ + t) * I_SZ + half;
        #pragma unroll 4
        for (int q = 0; q < 64; q++) {
            __nv_bfloat16 hi, lo;
            split_bf16(xr[q], hi, lo);
            Ax[r * SA3 + half + q]       = hi;
            Ax[r * SA3 + 128 + half + q] = lo;
        }
    }
    // stage B = pre-split W^T [128 n][128 k] (coalesced u32 loads, row STS)
    {
        const int n2  = tid >> 1;
        const int kh2 = (tid & 1) * 64;
        const uint32_t* src = g_wxt[g] + (size_t)(hb + n2) * 128 + kh2;
        #pragma unroll 4
        for (int q = 0; q < 64; q += 2) {
            uint32_t u0 = __ldcg(src + q), u1 = __ldcg(src + q + 1);
            *(uint32_t*)&Bw[n2 * SA3 + kh2 + q]       = (u0 & 0xffffu) | (u1 << 16);
            *(uint32_t*)&Bw[n2 * SA3 + 128 + kh2 + q] = (u0 >> 16) | (u1 & 0xffff0000u);
        }
    }
    __syncthreads();

    const uint32_t a_lane = smem_u32(Ax) +
        (uint32_t)(((16 * w + (l & 7) + 8 * ((l >> 3) & 1)) * SA3 + 8 * (l >> 4)) * 2);
    const uint32_t b_lane = smem_u32(Bw) +
        (uint32_t)((((l & 7) + 8 * (l >> 4)) * SA3 + 8 * ((l >> 3) & 1)) * 2);

    float acc[16][4];
    #pragma unroll
    for (int i = 0; i < 16; i++)
        #pragma unroll
        for (int j = 0; j < 4; j++) acc[i][j] = 0.0f;

    #pragma unroll 2
    for (int kc = 0; kc < 8; kc++) {
        uint32_t ah[4], al[4];
        ldsm4(ah, a_lane + kc * 32);
        ldsm4(al, a_lane + 256 + kc * 32);
        #pragma unroll
        for (int nt = 0; nt < 8; nt++) {
            uint32_t bh4[4], bl4[4];
            uint32_t ba = b_lane + (uint32_t)(nt * 16 * SA3 * 2) + kc * 32;
            ldsm4(bh4, ba);
            ldsm4(bl4, ba + 256);
            mma16816(acc[2 * nt],     ah, bh4 + 0);
            mma16816(acc[2 * nt + 1], ah, bh4 + 2);
            mma16816(acc[2 * nt],     al, bh4 + 0);
            mma16816(acc[2 * nt + 1], al, bh4 + 2);
            mma16816(acc[2 * nt],     ah, bl4 + 0);
            mma16816(acc[2 * nt + 1], ah, bl4 + 2);
        }
    }

    {
        const size_t row0 = (size_t)t * B_SZ + bh + 16 * w + (l >> 2);
        const int    cb   = g * 256 + hb + (l & 3) * 2;
        #pragma unroll
        for (int nt = 0; nt < 8; nt++) {
            *(float2*)&g_xproj[row0 * 1024 + cb + nt * 16]           = make_float2(acc[2*nt][0], acc[2*nt][1]);
            *(float2*)&g_xproj[(row0 + 8) * 1024 + cb + nt * 16]     = make_float2(acc[2*nt][2], acc[2*nt][3]);
            *(float2*)&g_xproj[row0 * 1024 + cb + nt * 16 + 8]       = make_float2(acc[2*nt+1][0], acc[2*nt+1][1]);
            *(float2*)&g_xproj[(row0 + 8) * 1024 + cb + nt * 16 + 8] = make_float2(acc[2*nt+1][2], acc[2*nt+1][3]);
        }
    }
}

// ================= recurrent kernel: 2 interleaved groups, mbarrier sync =================
__global__ void __launch_bounds__(THREADS2, 1) __cluster_dims__(CLC, 1, 1)
lstm_rec_kernel(const float* __restrict__ Wf_h,  const float* __restrict__ bf,
                const float* __restrict__ Wip_h, const float* __restrict__ bip,
                const float* __restrict__ Wit_h, const float* __restrict__ bit_,
                const float* __restrict__ Wo_h,  const float* __restrict__ bo,
                float* __restrict__ out)
{
    extern __shared__ char smem[];
    __nv_bfloat16* As  = (__nv_bfloat16*)smem;
    float*         scr = (float*)(smem + SCR_OFF2);    // [2 ks][128][12]
    const uint32_t sb  = smem_u32(smem);

    const int tid = threadIdx.x;
    const int w   = tid >> 5;
    const int l   = tid & 31;
    const int m   = w & 7;                  // M-tile (16 gate rows)
    const int ks  = w >> 3;                 // K half
    const int cc  = blockIdx.x & (CLC - 1);
    const int grp = blockIdx.x >> 3;
    const int b0  = grp * 16;               // cluster batch base (16 rows = 2 groups)

    // ---- mbarrier init (count = 8 arrives per phase) ----
    if (tid == 0) {
        mbar_init(sb + MBAR_OFF, CLC);
        mbar_init(sb + MBAR_OFF + 8, CLC);
    }

    // ---- stage A (short-part weights, K=256) hi|lo into SMEM ----
    {
        const int r  = tid >> 2;            // row = 4*h_local + gate
        const int kq = (tid & 3) * 64;
        const int g  = r & 3;
        const int hs = 32 * cc + (r >> 2);
        const float* Wh = (g == 0) ? Wf_h : (g == 1) ? Wip_h : (g == 2) ? Wit_h : Wo_h;
        #pragma unroll 4
        for (int k = kq; k < kq + 64; k++) {
            __nv_bfloat16 hi, lo;
            split_bf16(Wh[(size_t)k * H_SZ + hs], hi, lo);
            As[r * SA2 + k]       = hi;
            As[r * SA2 + 256 + k] = lo;
        }
    }
    // ---- zero step-0 short buffer (own slice: 2 groups x 8 rows x 32 h) ----
    {
        const int gz = tid >> 8, rz = (tid >> 5) & 7, hz = tid & 31;
        __stcg(&g_short_pack[0][(size_t)(b0 + gz * NBG + rz) * H_SZ + 32 * cc + hz], 0u);
    }
    __syncthreads();

    // ---- load A fragments into registers (once) ----
    uint32_t ahf[8][4], alf[8][4];
    {
        const uint32_t a_lane = sb +
            (uint32_t)(((16 * m + (l & 7) + 8 * ((l >> 3) & 1)) * SA2 + 8 * (l >> 4)) * 2);
        #pragma unroll
        for (int kc = 0; kc < 8; kc++) {
            ldsm2(ahf[kc] + 0, a_lane + (ks * 8 + kc) * 32);
            ldsm2(ahf[kc] + 2, a_lane + (ks * 8 + kc) * 32 + (uint32_t)(8 * (l >= 16 ? 0 : 0)) );
        }
        // proper x4 loads (two halves of A frag come from the x4 pattern)
        #pragma unroll
        for (int kc = 0; kc < 8; kc++) {
            ldsm4(ahf[kc], a_lane + (ks * 8 + kc) * 32);
            ldsm4(alf[kc], a_lane + 512 + (ks * 8 + kc) * 32);
        }
    }

    // B lane address part (x2: lanes 0-15 meaningful)
    const uint32_t b_lane_part = (uint32_t)((((l & 7)) * SB2 + ((l >> 3) & 1) * 8) * 2);

    // ---- epilogue mapping: tid<256: hl = tid>>3 (0..31), bb = tid&7 ----
    const int hl = tid >> 3;
    const int bb = tid & 7;
    const int hg = 32 * cc + (hl & 31);
    float bfv = 0.f, bipv = 0.f, bitv = 0.f, bov = 0.f;
    if (tid < 256) { bfv = bf[hg]; bipv = bip[hg]; bitv = bit_[hg]; bov = bo[hg]; }
    float longv[2] = {0.0f, 0.0f};

    __threadfence();
    __syncthreads();
    cluster_sync();

    #pragma unroll 1
    for (int t = 0; t < T_SZ; t++) {
        const int cur = t & 1;
        const int nxt = cur ^ 1;

        // prefetch x-projections for both groups (independent of recurrence)
        float xpv[2][4];
        if (tid < 256) {
            #pragma unroll
            for (int g2 = 0; g2 < 2; g2++) {
                const float* xr = g_xproj + ((size_t)t * B_SZ + b0 + g2 * NBG + bb) * 1024 + hg;
                #pragma unroll
                for (int g = 0; g < 4; g++) xpv[g2][g] = __ldcg(xr + g * 256);
            }
        }

        #pragma unroll
        for (int g2 = 0; g2 < 2; g2++) {
            const uint32_t mbar = sb + MBAR_OFF + g2 * 8;
            const uint32_t bsbase = sb + B_OFF2 + g2 * BG_BYTES;
            __nv_bfloat16* Bsg = (__nv_bfloat16*)(smem + B_OFF2 + g2 * BG_BYTES);

            // wait for peers' step-t short state (phase t-1)
            if (t > 0) mbar_wait_parity(mbar, (t - 1) & 1);

            // ===== stage B tile [8 rows][256 h] from L2 =====
            {
                const int row = tid >> 6;                 // 0..7
                const int cb  = (tid & 63) * 4;           // 4 h per thread
                uint4 v = __ldcg((const uint4*)(g_short_pack[cur] +
                           (size_t)(b0 + g2 * NBG + row) * H_SZ + cb));
                uint32_t hi01 = __byte_perm(v.x, v.y, 0x5410);
                uint32_t lo01 = __byte_perm(v.x, v.y, 0x7632);
                uint32_t hi23 = __byte_perm(v.z, v.w, 0x5410);
                uint32_t lo23 = __byte_perm(v.z, v.w, 0x7632);
                __nv_bfloat16* brow = Bsg + row * SB2;
                *(uint2*)&brow[cb]       = make_uint2(hi01, hi23);
                *(uint2*)&brow[256 + cb] = make_uint2(lo01, lo23);
            }
            __syncthreads();

            // ===== GEMM: M=128, N=8, K=256, 3-term split =====
            float acch[4] = {0.f, 0.f, 0.f, 0.f};
            float accc[4] = {0.f, 0.f, 0.f, 0.f};
            {
                const uint32_t bl = bsbase + b_lane_part;
                #pragma unroll
                for (int kc = 0; kc < 8; kc++) {
                    uint32_t bh2[2], bl2[2];
                    const uint32_t kb = (uint32_t)(ks * 8 + kc) * 32;
                    ldsm2(bh2, bl + kb);
                    ldsm2(bl2, bl + 512 + kb);
                    mma16816(acch, ahf[kc], bh2);
                    mma16816(accc, alf[kc], bh2);
                    mma16816(accc, ahf[kc], bl2);
                }
            }

            // ===== K-split partials -> scratch =====
            {
                float* s = scr + ks * (128 * SCR_S);
                const int r0 = 16 * m + (l >> 2);
                const int c0 = (l & 3) * 2;
                *(float2*)&s[r0 * SCR_S + c0]       = make_float2(acch[0] + accc[0], acch[1] + accc[1]);
                *(float2*)&s[(r0 + 8) * SCR_S + c0] = make_float2(acch[2] + accc[2], acch[3] + accc[3]);
            }
            __syncthreads();

            // ===== epilogue (tid<256): 1 cell (hl, bb) =====
            if (tid < 256) {
                float z[4];
                #pragma unroll
                for (int g = 0; g < 4; g++) {
                    const int r = 4 * hl + g;
                    z[g] = scr[r * SCR_S + bb] + scr[128 * SCR_S + r * SCR_S + bb]
                         + xpv[g2][g] + ((g == 0) ? bfv : (g == 1) ? bipv : (g == 2) ? bitv : bov);
                }
                float f  = sigm(z[0]);
                float ip = sigm(z[1]);
                float pt = tanh_(z[2]);
                longv[g2] = f * longv[g2] + ip * pt;
                float o  = sigm(z[3]);
                float ns = tanh_(longv[g2]) * o;

                __nv_bfloat16 hi, lo;
                split_bf16(ns, hi, lo);
                uint32_t pk = (uint32_t)__bfloat16_as_ushort(hi) |
                              ((uint32_t)__bfloat16_as_ushort(lo) << 16);
                const int bbg = b0 + g2 * NBG + bb;
                __stcg(&g_short_pack[nxt][(size_t)bbg * H_SZ + hg], pk);
                __threadfence();   // make store visible before the arrive below

                if (t == T_SZ - 1) {
                    out[(size_t)bbg * H_SZ + hg]                       = ns;
                    out[(size_t)B_SZ * H_SZ + (size_t)bbg * H_SZ + hg] = longv[g2];
                }
            }
            __syncthreads();

            // signal all peers (incl. self): this CTA's slice for step t is published
            if (tid == 0 && t < T_SZ - 1) {
                #pragma unroll
                for (int d = 0; d < CLC; d++) mbar_arrive_cluster(mbar, d);
            }
        }
    }
    cluster_sync();  // keep cluster SMEM alive until all remote ops settle
}

// ---------------- launch ----------------
extern "C" void kernel_launch(void* const* d_in, const int* in_sizes, int n_in,
                              void* d_out, int out_size)
{
    (void)in_sizes; (void)n_in; (void)out_size;
    const float* x     = (const float*)d_in[0];
    const float* Wf_h  = (const float*)d_in[1];
    const float* Wf_x  = (const float*)d_in[2];
    const float* bf    = (const float*)d_in[3];
    const float* Wip_h = (const float*)d_in[4];
    const float* Wip_x = (const float*)d_in[5];
    const float* bip   = (const float*)d_in[6];
    const float* Wit_h = (const float*)d_in[7];
    const float* Wit_x = (const float*)d_in[8];
    const float* bit_  = (const float*)d_in[9];
    const float* Wo_h  = (const float*)d_in[10];
    const float* Wo_x  = (const float*)d_in[11];
    const float* bo    = (const float*)d_in[12];
    float* out = (float*)d_out;

    cudaFuncSetAttribute(xproj_kernel,
                         cudaFuncAttributeMaxDynamicSharedMemorySize, SMEM3);
    cudaFuncSetAttribute(lstm_rec_kernel,
                         cudaFuncAttributeMaxDynamicSharedMemorySize, SMEM2);

    wsplit_kernel<<<4, 256>>>(Wf_x, Wip_x, Wit_x, Wo_x);

    dim3 pgrid(2048, 8);
    xproj_kernel<<<pgrid, 256, SMEM3>>>(x);

    lstm_rec_kernel<<<GRID_CTAS, THREADS2, SMEM2>>>(
        Wf_h, bf, Wip_h, bip, Wit_h, bit_, Wo_h, bo, out);
}

// round 9
// speedup vs baseline: 1.9390x; 1.2964x over previous
#include <cuda_runtime.h>
#include <cuda_bf16.h>
#include <cstdint>
#include <cstddef>

// ---------------- problem constants ----------------
#define B_SZ   256
#define T_SZ   1024
#define I_SZ   128
#define H_SZ   256
#define CLC    8                 // CTAs per cluster (hidden split)
#define GRID_CTAS 128
#define THREADS2 512             // recurrent kernel: 16 warps = 2 groups
#define NBG    8                 // batch rows per group

// ---------------- recurrent kernel SMEM ----------------
#define SA2 520                              // 1040B = 65*16B odd -> conflict-free ldmatrix
#define SB2 520
#define A_BYTES2  (128 * SA2 * 2)            // 133120
#define B_OFF2    A_BYTES2
#define BG_BYTES  (NBG * SB2 * 2)            // 8320 per group tile
#define SCR_OFF2  (B_OFF2 + 2 * BG_BYTES)    // 149760
#define SCR_S     12
#define SCRG      (128 * SCR_S)              // floats per group scratch
#define MBAR_OFF  (SCR_OFF2 + 2 * SCRG * 4)  // 162048
#define SMEM2     (MBAR_OFF + 64)            // 162112

// ---------------- precompute kernel SMEM ----------------
#define SA3 264                              // 528B = 33*16B odd
#define PC_A_BYTES (128 * SA3 * 2)           // 67584 (x tile, M=128)
#define PC_B_BYTES (256 * SA3 * 2)           // 135168 (W tile, N=256)
#define SMEM3 (PC_A_BYTES + PC_B_BYTES)      // 202752

// x-projection scratch: xp[t*B + b][g*256 + h], fp32, 1 GiB
__device__ float g_xproj[268435456];
// packed (hi | lo<<16) bf16 short-state exchange, ping-pong, in L2
__device__ uint32_t g_short_pack[2][B_SZ * H_SZ];
// pre-split, transposed x-weights: [gate][h=256][k=128] packed (hi | lo<<16)
__device__ uint32_t g_wxt[4][256 * 128];

// ---------------- helpers ----------------
__device__ __forceinline__ uint32_t smem_u32(const void* p) {
    uint32_t a;
    asm("{ .reg .u64 t; cvta.to.shared.u64 t, %1; cvt.u32.u64 %0, t; }" : "=r"(a) : "l"(p));
    return a;
}
__device__ __forceinline__ void cluster_sync() {
    asm volatile("barrier.cluster.arrive.aligned;" ::: "memory");
    asm volatile("barrier.cluster.wait.aligned;"   ::: "memory");
}
__device__ __forceinline__ void bar_named(int id, int cnt) {
    asm volatile("bar.sync %0, %1;" :: "r"(id), "r"(cnt) : "memory");
}
__device__ __forceinline__ void ldsm4(uint32_t* r, uint32_t addr) {
    asm volatile("ldmatrix.sync.aligned.m8n8.x4.shared.b16 {%0,%1,%2,%3}, [%4];"
                 : "=r"(r[0]), "=r"(r[1]), "=r"(r[2]), "=r"(r[3]) : "r"(addr));
}
__device__ __forceinline__ void ldsm2(uint32_t* r, uint32_t addr) {
    asm volatile("ldmatrix.sync.aligned.m8n8.x2.shared.b16 {%0,%1}, [%2];"
                 : "=r"(r[0]), "=r"(r[1]) : "r"(addr));
}
__device__ __forceinline__ void mma16816(float* d, const uint32_t* a, const uint32_t* b) {
    asm volatile("mma.sync.aligned.m16n8k16.row.col.f32.bf16.bf16.f32 "
                 "{%0,%1,%2,%3}, {%4,%5,%6,%7}, {%8,%9}, {%0,%1,%2,%3};"
                 : "+f"(d[0]), "+f"(d[1]), "+f"(d[2]), "+f"(d[3])
                 : "r"(a[0]), "r"(a[1]), "r"(a[2]), "r"(a[3]), "r"(b[0]), "r"(b[1]));
}
__device__ __forceinline__ void mbar_init(uint32_t mbar, uint32_t cnt) {
    asm volatile("mbarrier.init.shared.b64 [%0], %1;" :: "r"(mbar), "r"(cnt) : "memory");
}
__device__ __forceinline__ void mbar_arrive_cluster(uint32_t local_mbar, uint32_t rank) {
    asm volatile("{\n\t.reg .b32 ra;\n\t"
                 "mapa.shared::cluster.u32 ra, %0, %1;\n\t"
                 "mbarrier.arrive.shared::cluster.b64 _, [ra];\n\t}"
                 :: "r"(local_mbar), "r"(rank) : "memory");
}
__device__ __forceinline__ void mbar_wait_parity(uint32_t mbar, uint32_t parity) {
    asm volatile("{\n\t.reg .pred P1;\n\t"
                 "WAIT_LOOP_%=:\n\t"
                 "mbarrier.try_wait.parity.acquire.cluster.shared::cta.b64 P1, [%0], %1, 0x989680;\n\t"
                 "@P1 bra.uni WAIT_DONE_%=;\n\t"
                 "bra.uni WAIT_LOOP_%=;\n\t"
                 "WAIT_DONE_%=:\n\t}" :: "r"(mbar), "r"(parity) : "memory");
}
__device__ __forceinline__ float sigm(float x) {
    return __fdividef(1.0f, 1.0f + __expf(-x));
}
__device__ __forceinline__ float tanh_(float x) {
    float e = __expf(-2.0f * fabsf(x));
    return copysignf(__fdividef(1.0f - e, 1.0f + e), x);
}
__device__ __forceinline__ void split_bf16(float v, __nv_bfloat16& hi, __nv_bfloat16& lo) {
    hi = __float2bfloat16_rn(v);
    lo = __float2bfloat16_rn(v - __bfloat162float(hi));
}

// ================= wsplit: Wx -> split/transposed packed global =================
__global__ void __launch_bounds__(256)
wsplit_kernel(const float* __restrict__ Wf_x, const float* __restrict__ Wip_x,
              const float* __restrict__ Wit_x, const float* __restrict__ Wo_x)
{
    const int g = blockIdx.x >> 5;            // 4 gates x 32 chunks
    const int chunk = blockIdx.x & 31;
    const float* W = (g == 0) ? Wf_x : (g == 1) ? Wip_x : (g == 2) ? Wit_x : Wo_x;
    const int i = chunk * 1024 + threadIdx.x * 4;
    #pragma unroll
    for (int q = 0; q < 4; q++) {
        const int n = (i + q) >> 7, k = (i + q) & 127;
        float v = W[(size_t)k * H_SZ + n];
        __nv_bfloat16 hi, lo;
        split_bf16(v, hi, lo);
        g_wxt[g][i + q] = (uint32_t)__bfloat16_as_ushort(hi) |
                          ((uint32_t)__bfloat16_as_ushort(lo) << 16);
    }
}

// ================= precompute: xp = x @ Wx ; block = (t, batch-half) x gate, N=256 =================
__global__ void __launch_bounds__(256, 1)
xproj_kernel(const float* __restrict__ x)
{
    extern __shared__ char smem[];
    __nv_bfloat16* Ax = (__nv_bfloat16*)smem;                  // [128][264] hi|lo
    __nv_bfloat16* Bw = (__nv_bfloat16*)(smem + PC_A_BYTES);   // [256][264] hi|lo

    const int tid = threadIdx.x;
    const int w   = tid >> 5;
    const int l   = tid & 31;
    const int t   = blockIdx.x >> 1;
    const int bh  = (blockIdx.x & 1) * 128;          // batch half
    const int g   = blockIdx.y;

    // stage A = x block [128 b][128 i], hi/lo
    {
        const int r    = tid >> 1;
        const int half = (tid & 1) * 64;
        const float* xr = x + ((size_t)(bh + r) * T_SZ + t) * I_SZ + half;
        #pragma unroll 4
        for (int q = 0; q < 64; q++) {
            __nv_bfloat16 hi, lo;
            split_bf16(xr[q], hi, lo);
            Ax[r * SA3 + half + q]       = hi;
            Ax[r * SA3 + 128 + half + q] = lo;
        }
    }
    // stage B = pre-split W^T [256 n][128 k]
    {
        const uint32_t* src = g_wxt[g] + (size_t)tid * 128;
        #pragma unroll 4
        for (int q = 0; q < 128; q += 2) {
            uint32_t u0 = __ldcg(src + q), u1 = __ldcg(src + q + 1);
            *(uint32_t*)&Bw[tid * SA3 + q]       = (u0 & 0xffffu) | (u1 << 16);
            *(uint32_t*)&Bw[tid * SA3 + 128 + q] = (u0 >> 16) | (u1 & 0xffff0000u);
        }
    }
    __syncthreads();

    const uint32_t a_lane = smem_u32(Ax) +
        (uint32_t)(((16 * w + (l & 7) + 8 * ((l >> 3) & 1)) * SA3 + 8 * (l >> 4)) * 2);
    const uint32_t b_lane = smem_u32(Bw) +
        (uint32_t)((((l & 7) + 8 * (l >> 4)) * SA3 + 8 * ((l >> 3) & 1)) * 2);

    float acc[32][4];
    #pragma unroll
    for (int i = 0; i < 32; i++)
        #pragma unroll
        for (int j = 0; j < 4; j++) acc[i][j] = 0.0f;

    #pragma unroll 1
    for (int kc = 0; kc < 8; kc++) {
        uint32_t ah[4], al[4];
        ldsm4(ah, a_lane + kc * 32);
        ldsm4(al, a_lane + 256 + kc * 32);
        #pragma unroll
        for (int nt = 0; nt < 16; nt++) {
            uint32_t bh4[4], bl4[4];
            uint32_t ba = b_lane + (uint32_t)(nt * 16 * SA3 * 2) + kc * 32;
            ldsm4(bh4, ba);
            ldsm4(bl4, ba + 256);
            mma16816(acc[2 * nt],     ah, bh4 + 0);
            mma16816(acc[2 * nt + 1], ah, bh4 + 2);
            mma16816(acc[2 * nt],     al, bh4 + 0);
            mma16816(acc[2 * nt + 1], al, bh4 + 2);
            mma16816(acc[2 * nt],     ah, bl4 + 0);
            mma16816(acc[2 * nt + 1], ah, bl4 + 2);
        }
    }

    {
        const size_t row0 = (size_t)t * B_SZ + bh + 16 * w + (l >> 2);
        const int    cb   = g * 256 + (l & 3) * 2;
        #pragma unroll
        for (int nt = 0; nt < 16; nt++) {
            *(float2*)&g_xproj[row0 * 1024 + cb + nt * 16]           = make_float2(acc[2*nt][0], acc[2*nt][1]);
            *(float2*)&g_xproj[(row0 + 8) * 1024 + cb + nt * 16]     = make_float2(acc[2*nt][2], acc[2*nt][3]);
            *(float2*)&g_xproj[row0 * 1024 + cb + nt * 16 + 8]       = make_float2(acc[2*nt+1][0], acc[2*nt+1][1]);
            *(float2*)&g_xproj[(row0 + 8) * 1024 + cb + nt * 16 + 8] = make_float2(acc[2*nt+1][2], acc[2*nt+1][3]);
        }
    }
}

// ================= recurrent kernel: 2 warp-specialized groups =================
__global__ void __launch_bounds__(THREADS2, 1) __cluster_dims__(CLC, 1, 1)
lstm_rec_kernel(const float* __restrict__ Wf_h,  const float* __restrict__ bf,
                const float* __restrict__ Wip_h, const float* __restrict__ bip,
                const float* __restrict__ Wit_h, const float* __restrict__ bit_,
                const float* __restrict__ Wo_h,  const float* __restrict__ bo,
                float* __restrict__ out)
{
    extern __shared__ char smem[];
    __nv_bfloat16* As = (__nv_bfloat16*)smem;
    const uint32_t sb = smem_u32(smem);

    const int tid  = threadIdx.x;
    const int w    = tid >> 5;
    const int l    = tid & 31;
    const int wg   = w >> 3;                 // group 0/1
    const int wl   = w & 7;                  // M-tile within group
    const int tidg = tid & 255;              // thread id within group
    const int cc   = blockIdx.x & (CLC - 1);
    const int grp  = blockIdx.x >> 3;
    const int b0   = grp * 16;
    const int gb   = b0 + wg * NBG;          // group batch base

    // ---- mbarrier init ----
    if (tid == 0) { mbar_init(sb + MBAR_OFF, CLC); mbar_init(sb + MBAR_OFF + 8, CLC); }

    // ---- stage A (short-part weights, K=256) hi|lo ----
    {
        const int r  = tid >> 2;
        const int kq = (tid & 3) * 64;
        const int g  = r & 3;
        const int hs = 32 * cc + (r >> 2);
        const float* Wh = (g == 0) ? Wf_h : (g == 1) ? Wip_h : (g == 2) ? Wit_h : Wo_h;
        #pragma unroll 4
        for (int k = kq; k < kq + 64; k++) {
            __nv_bfloat16 hi, lo;
            split_bf16(Wh[(size_t)k * H_SZ + hs], hi, lo);
            As[r * SA2 + k]       = hi;
            As[r * SA2 + 256 + k] = lo;
        }
    }
    // ---- zero step-0 short buffer (own slice) ----
    {
        const int gz = tid >> 8, rz = (tid >> 5) & 7, hz = tid & 31;
        __stcg(&g_short_pack[0][(size_t)(b0 + gz * NBG + rz) * H_SZ + 32 * cc + hz], 0u);
    }
    __syncthreads();

    // ---- A-hi frags to registers (once); A-lo stays in SMEM ----
    const uint32_t a_lane = sb +
        (uint32_t)(((16 * wl + (l & 7) + 8 * ((l >> 3) & 1)) * SA2 + 8 * (l >> 4)) * 2);
    uint32_t ahf[16][4];
    #pragma unroll
    for (int kc = 0; kc < 16; kc++) ldsm4(ahf[kc], a_lane + kc * 32);

    const uint32_t bsbase = sb + B_OFF2 + (uint32_t)wg * BG_BYTES;
    const uint32_t b_lane = bsbase + (uint32_t)(((l & 7) * SB2 + ((l >> 3) & 1) * 8) * 2);
    float* scr = (float*)(smem + SCR_OFF2) + wg * SCRG;
    const uint32_t mbar = sb + MBAR_OFF + wg * 8;
    const int barid = wg + 1;

    // ---- epilogue mapping: cell (hl, bb) within group ----
    const int hl = tidg >> 3;
    const int bb = tidg & 7;
    const int hg = 32 * cc + hl;
    const float biasv[4] = {bf[hg], bip[hg], bit_[hg], bo[hg]};
    float longv = 0.0f;

    __threadfence();
    __syncthreads();
    cluster_sync();

    #pragma unroll 1
    for (int t = 0; t < T_SZ; t++) {
        const int cur = t & 1;
        const int nxt = cur ^ 1;

        // prefetch x-projection (independent of exchange)
        float xpv[4];
        {
            const float* xr = g_xproj + ((size_t)t * B_SZ + gb + bb) * 1024 + hg;
            #pragma unroll
            for (int g = 0; g < 4; g++) xpv[g] = __ldcg(xr + g * 256);
        }

        // wait for peers' step-t short state
        if (t > 0) mbar_wait_parity(mbar, (t - 1) & 1);

        // ===== stage B tile [8 rows][256 h] from L2 =====
        {
            const int row = tidg >> 5;
            const int hb8 = (tidg & 31) * 8;
            const uint32_t* srow = g_short_pack[cur] + (size_t)(gb + row) * H_SZ + hb8;
            uint4 v0 = __ldcg((const uint4*)srow);
            uint4 v1 = __ldcg((const uint4*)(srow + 4));
            __nv_bfloat16* brow = (__nv_bfloat16*)(smem + B_OFF2 + wg * BG_BYTES) + row * SB2;
            *(uint2*)&brow[hb8]           = make_uint2(__byte_perm(v0.x, v0.y, 0x5410),
                                                       __byte_perm(v0.z, v0.w, 0x5410));
            *(uint2*)&brow[hb8 + 4]       = make_uint2(__byte_perm(v1.x, v1.y, 0x5410),
                                                       __byte_perm(v1.z, v1.w, 0x5410));
            *(uint2*)&brow[256 + hb8]     = make_uint2(__byte_perm(v0.x, v0.y, 0x7632),
                                                       __byte_perm(v0.z, v0.w, 0x7632));
            *(uint2*)&brow[256 + hb8 + 4] = make_uint2(__byte_perm(v1.x, v1.y, 0x7632),
                                                       __byte_perm(v1.z, v1.w, 0x7632));
        }
        bar_named(barid, 256);

        // ===== GEMM: M=128, N=8, K=256; A-hi in regs, A-lo/B via ldsm =====
        float acch[4] = {0.f, 0.f, 0.f, 0.f};
        float accc[4] = {0.f, 0.f, 0.f, 0.f};
        #pragma unroll
        for (int kc = 0; kc < 16; kc++) {
            uint32_t bh2[2], bl2[2], alo[4];
            const uint32_t kb = (uint32_t)kc * 32;
            ldsm2(bh2, b_lane + kb);
            ldsm2(bl2, b_lane + 512 + kb);
            ldsm4(alo, a_lane + 512 + kb);
            mma16816(acch, ahf[kc], bh2);
            mma16816(accc, alo,     bh2);
            mma16816(accc, ahf[kc], bl2);
        }

        // ===== partials -> scratch =====
        {
            const int r0 = 16 * wl + (l >> 2);
            const int c0 = (l & 3) * 2;
            *(float2*)&scr[r0 * SCR_S + c0]       = make_float2(acch[0] + accc[0], acch[1] + accc[1]);
            *(float2*)&scr[(r0 + 8) * SCR_S + c0] = make_float2(acch[2] + accc[2], acch[3] + accc[3]);
        }
        bar_named(barid, 256);

        // ===== epilogue: 1 cell (hl, bb) =====
        {
            float z[4];
            #pragma unroll
            for (int g = 0; g < 4; g++)
                z[g] = scr[(4 * hl + g) * SCR_S + bb] + xpv[g] + biasv[g];
            float f  = sigm(z[0]);
            float ip = sigm(z[1]);
            float pt = tanh_(z[2]);
            longv = f * longv + ip * pt;
            float o  = sigm(z[3]);
            float ns = tanh_(longv) * o;

            __nv_bfloat16 hi, lo;
            split_bf16(ns, hi, lo);
            uint32_t pk = (uint32_t)__bfloat16_as_ushort(hi) |
                          ((uint32_t)__bfloat16_as_ushort(lo) << 16);
            const int bbg = gb + bb;
            __stcg(&g_short_pack[nxt][(size_t)bbg * H_SZ + hg], pk);

            if (t == T_SZ - 1) {
                out[(size_t)bbg * H_SZ + hg]                       = ns;
                out[(size_t)B_SZ * H_SZ + (size_t)bbg * H_SZ + hg] = longv;
            }
        }
        bar_named(barid, 256);

        // publish: one gpu-scope fence + remote arrives (tid 0 of group)
        if (tidg == 0 && t < T_SZ - 1) {
            asm volatile("fence.acq_rel.gpu;" ::: "memory");
            #pragma unroll
            for (int d = 0; d < CLC; d++) mbar_arrive_cluster(mbar, d);
        }
    }
    cluster_sync();  // keep SMEM alive for in-flight remote arrives
}

// ---------------- launch ----------------
extern "C" void kernel_launch(void* const* d_in, const int* in_sizes, int n_in,
                              void* d_out, int out_size)
{
    (void)in_sizes; (void)n_in; (void)out_size;
    const float* x     = (const float*)d_in[0];
    const float* Wf_h  = (const float*)d_in[1];
    const float* Wf_x  = (const float*)d_in[2];
    const float* bf    = (const float*)d_in[3];
    const float* Wip_h = (const float*)d_in[4];
    const float* Wip_x = (const float*)d_in[5];
    const float* bip   = (const float*)d_in[6];
    const float* Wit_h = (const float*)d_in[7];
    const float* Wit_x = (const float*)d_in[8];
    const float* bit_  = (const float*)d_in[9];
    const float* Wo_h  = (const float*)d_in[10];
    const float* Wo_x  = (const float*)d_in[11];
    const float* bo    = (const float*)d_in[12];
    float* out = (float*)d_out;

    cudaFuncSetAttribute(xproj_kernel,
                         cudaFuncAttributeMaxDynamicSharedMemorySize, SMEM3);
    cudaFuncSetAttribute(lstm_rec_kernel,
                         cudaFuncAttributeMaxDynamicSharedMemorySize, SMEM2);

    wsplit_kernel<<<128, 256>>>(Wf_x, Wip_x, Wit_x, Wo_x);

    dim3 pgrid(2048, 4);
    xproj_kernel<<<pgrid, 256, SMEM3>>>(x);

    lstm_rec_kernel<<<GRID_CTAS, THREADS2, SMEM2>>>(
        Wf_h, bf, Wip_h, bip, Wit_h, bit_, Wo_h, bo, out);
}